// round 5
// baseline (speedup 1.0000x reference)
#include <cuda_runtime.h>
#include <cstdint>
#include <math.h>

#define BLOCKT  512
#define SAMPB   128          // samples per block (4 threads each)
#define KDIM    784
#define KPAD    800
#define TILE_K  32
#define NT      25           // 25*32 = 800 (zero-filled past 784)
#define XSTRIDE 36           // 32 + 4 pad -> conflict-free LDS.128
#define BUF     (SAMPB*XSTRIDE)    // 4608 floats per stage
#define STAGES  3
#define W1SZ    3600         // 900 float4 slots: r + (r>>3) interleave for 800 rows

// smem floats: xs[3][BUF] + w1s[3600] + sw[240] = 17664 floats = 70.7KB
#define SMEM_FLOATS (STAGES*BUF + W1SZ + 240)

__device__ __forceinline__ void cp_async16(unsigned dst, const float* src, int src_sz) {
    asm volatile("cp.async.cg.shared.global [%0], [%1], 16, %2;\n"
                 :: "r"(dst), "l"(src), "r"(src_sz));
}
__device__ __forceinline__ void cp_commit() {
    asm volatile("cp.async.commit_group;\n" ::: "memory");
}
template<int N>
__device__ __forceinline__ void cp_wait() {
    asm volatile("cp.async.wait_group %0;\n" :: "n"(N) : "memory");
}

__global__ void __launch_bounds__(BLOCKT) qhybrid_kernel(
    const float* __restrict__ x,
    const float* __restrict__ W1, const float* __restrict__ b1,
    const float* __restrict__ qw,
    const float* __restrict__ W2, const float* __restrict__ b2,
    const float* __restrict__ W3, const float* __restrict__ b3,
    float* __restrict__ out, int B)
{
    extern __shared__ float smem[];
    float* xs  = smem;                    // [3][128][36]
    float* w1s = smem + STAGES * BUF;     // interleaved [900] float4
    float* sw  = w1s + W1SZ;              // small weights

    const int tid = threadIdx.x;
    const int sl  = tid >> 2;             // sample row 0..127
    const int qd  = tid & 3;              // K quarter 0..3
    const long sbase = (long)blockIdx.x * SAMPB;
    const long srowg = sbase + sl;
    const int  rok   = (srowg < (long)B) ? 16 : 0;
    const float* srow = x + srowg * (long)KDIM;

    const unsigned xs_u32 = (unsigned)__cvta_generic_to_shared(xs);
    const unsigned dst0   = xs_u32 + (unsigned)((sl * XSTRIDE + qd * 8) * 4);

    // ---- prologue: tiles 0 and 1 in flight ----
    #pragma unroll
    for (int kt = 0; kt < 2; kt++) {
        const int col0 = kt * TILE_K + qd * 8;      // < 784 here
        const unsigned d = dst0 + (unsigned)(kt * BUF * 4);
        cp_async16(d,      srow + col0,     rok);
        cp_async16(d + 16, srow + col0 + 4, rok);
        cp_commit();
    }

    // ---- preload W1 with bank-interleave: float4 slot r + (r>>3) ----
    for (int r = tid; r < KPAD; r += BLOCKT) {
        float4 v = make_float4(0.f, 0.f, 0.f, 0.f);
        if (r < KDIM) v = __ldg((const float4*)W1 + r);
        ((float4*)w1s)[r + (r >> 3)] = v;
    }
    // ---- small weights: b1@0(4) qw@4(8) W2@12(128) b2@140(32) W3@172(64) b3@236(2) ----
    if (tid < 4)   sw[tid]       = b1[tid];
    if (tid < 8)   sw[4 + tid]   = qw[tid];
    if (tid < 128) sw[12 + tid]  = W2[tid];
    if (tid < 32)  sw[140 + tid] = b2[tid];
    if (tid < 64)  sw[172 + tid] = W3[tid];
    if (tid < 2)   sw[236 + tid] = b3[tid];

    float acc[4] = {0.f, 0.f, 0.f, 0.f};

    // ---- GEMM mainloop: 3-stage pipeline, exact tail accounting ----
    #pragma unroll 1
    for (int kt = 0; kt < NT; kt++) {
        if (kt < NT - 1) cp_wait<1>();   // tile kt done (kt+1 may be in flight)
        else             cp_wait<0>();
        __syncthreads();                 // publish tile kt; close reads of kt-1

        const int kp = kt + 2;
        if (kp < NT) {                   // prefetch into buf (kt-1)%3, now free
            const int col0 = kp * TILE_K + qd * 8;
            const unsigned d = dst0 + (unsigned)((kp % 3) * BUF * 4);
            const int s0 = (col0     < KDIM) ? rok : 0;
            const int s1 = (col0 + 4 < KDIM) ? rok : 0;
            cp_async16(d,      srow + col0,     s0);
            cp_async16(d + 16, srow + col0 + 4, s1);
            cp_commit();
        }

        // compute: this thread's 8 columns of tile kt
        const float* xr = xs + (kt % 3) * BUF + sl * XSTRIDE + qd * 8;
        float4 xv0 = *(const float4*)(xr);
        float4 xv1 = *(const float4*)(xr + 4);
        const int r0 = kt * TILE_K + qd * 8;         // first W row
        const float4* wq = (const float4*)w1s + (r0 + (r0 >> 3));
        float xvals[8] = {xv0.x, xv0.y, xv0.z, xv0.w, xv1.x, xv1.y, xv1.z, xv1.w};
        #pragma unroll
        for (int j = 0; j < 8; j++) {
            float4 w = wq[j];            // rows r0..r0+7 contiguous (no gap inside 8)
            acc[0] = fmaf(xvals[j], w.x, acc[0]);
            acc[1] = fmaf(xvals[j], w.y, acc[1]);
            acc[2] = fmaf(xvals[j], w.z, acc[2]);
            acc[3] = fmaf(xvals[j], w.w, acc[3]);
        }
    }

    // ---- reduce the 4 K-quarters (lanes 4k..4k+3) ----
    #pragma unroll
    for (int j = 0; j < 4; j++) {
        acc[j] += __shfl_xor_sync(0xFFFFFFFFu, acc[j], 1);
        acc[j] += __shfl_xor_sync(0xFFFFFFFFu, acc[j], 2);
    }

    // ---- angles = relu(pre + b1) ----
    float cq[4], sq[4];
    #pragma unroll
    for (int q = 0; q < 4; q++) {
        float ang = fmaxf(acc[q] + sw[q], 0.f);
        __sincosf(0.5f * ang, &sq[q], &cq[q]);
    }

    // ---- 4-qubit statevector in registers ----
    float re[16], im[16];
    #pragma unroll
    for (int i = 0; i < 16; i++) {
        float m = 1.f;
        #pragma unroll
        for (int q = 0; q < 4; q++) m *= ((i >> (3 - q)) & 1) ? sq[q] : cq[q];
        int k = __popc(i) & 3;  // phase (-i)^k
        re[i] = (k == 0) ? m : ((k == 2) ? -m : 0.f);
        im[i] = (k == 1) ? -m : ((k == 3) ? m : 0.f);
    }

    // ---- BasicEntanglerLayers: RX(w[l,q]) then CNOT ring ----
    #pragma unroll
    for (int l = 0; l < 2; l++) {
        #pragma unroll
        for (int q = 0; q < 4; q++) {
            float cg, sg;
            __sincosf(0.5f * sw[4 + l * 4 + q], &sg, &cg);
            const int mask = 8 >> q;
            #pragma unroll
            for (int i = 0; i < 16; i++) {
                if (i & mask) continue;
                const int i1 = i | mask;
                float r0 = re[i], ii0 = im[i], r1 = re[i1], ii1 = im[i1];
                re[i]  = fmaf(cg, r0,  sg * ii1);
                im[i]  = fmaf(cg, ii0, -sg * r1);
                re[i1] = fmaf(cg, r1,  sg * ii0);
                im[i1] = fmaf(cg, ii1, -sg * r0);
            }
        }
        #pragma unroll
        for (int q = 0; q < 4; q++) {
            const int cmask = 8 >> q;
            const int tmask = 8 >> ((q + 1) & 3);
            #pragma unroll
            for (int i = 0; i < 16; i++) {
                if ((i & cmask) && !(i & tmask)) {
                    const int j = i | tmask;
                    float t = re[i]; re[i] = re[j]; re[j] = t;
                    t = im[i]; im[i] = im[j]; im[j] = t;
                }
            }
        }
    }

    // ---- <Z_q> expectation values ----
    float ez[4] = {0.f, 0.f, 0.f, 0.f};
    #pragma unroll
    for (int i = 0; i < 16; i++) {
        float p = re[i] * re[i] + im[i] * im[i];
        #pragma unroll
        for (int q = 0; q < 4; q++)
            ez[q] += ((i >> (3 - q)) & 1) ? -p : p;
    }
    #pragma unroll
    for (int q = 0; q < 4; q++)
        if (!(ez[q] == ez[q])) ez[q] = 0.f;  // NaN -> 0 (matches reference)

    // ---- post = relu(ez@W2 + b2); logits = post@W3 + b3; softmax ----
    float l0 = sw[236], l1 = sw[237];
    #pragma unroll
    for (int j = 0; j < 32; j++) {
        float pj = sw[140 + j];
        #pragma unroll
        for (int q = 0; q < 4; q++)
            pj = fmaf(ez[q], sw[12 + q * 32 + j], pj);
        pj = fmaxf(pj, 0.f);
        l0 = fmaf(pj, sw[172 + j * 2],     l0);
        l1 = fmaf(pj, sw[172 + j * 2 + 1], l1);
    }
    float mx = fmaxf(l0, l1);
    float e0 = __expf(l0 - mx);
    float e1 = __expf(l1 - mx);
    float inv = 1.f / (e0 + e1);

    if (qd == 0 && srowg < (long)B) {
        float2 o = make_float2(e0 * inv, e1 * inv);
        *(float2*)(out + srowg * 2) = o;
    }
}

extern "C" void kernel_launch(void* const* d_in, const int* in_sizes, int n_in,
                              void* d_out, int out_size) {
    const float* x  = (const float*)d_in[0];
    const float* W1 = (const float*)d_in[1];
    const float* b1 = (const float*)d_in[2];
    const float* qw = (const float*)d_in[3];
    const float* W2 = (const float*)d_in[4];
    const float* b2 = (const float*)d_in[5];
    const float* W3 = (const float*)d_in[6];
    const float* b3 = (const float*)d_in[7];
    float* out = (float*)d_out;

    int B = in_sizes[0] / KDIM;
    int grid = (B + SAMPB - 1) / SAMPB;
    size_t smem_bytes = SMEM_FLOATS * sizeof(float);  // ~70.7 KB -> opt-in
    cudaFuncSetAttribute(qhybrid_kernel,
                         cudaFuncAttributeMaxDynamicSharedMemorySize,
                         (int)smem_bytes);
    qhybrid_kernel<<<grid, BLOCKT, smem_bytes>>>(x, W1, b1, qw, W2, b2, W3, b3, out, B);
}

// round 6
// speedup vs baseline: 1.5264x; 1.5264x over previous
#include <cuda_runtime.h>
#include <cstdint>
#include <math.h>

#define BLOCKT  64           // 2 warps per block, 64 samples
#define KDIM    784
#define KPAD    800
#define TILE_K  32
#define NT      25           // 25*32 = 800 (zero-filled past 784)
#define XSTRIDE 36           // 32 + 4 pad -> conflict-free LDS.128
#define STAGE   (32*XSTRIDE) // 1152 floats: one warp's 32-row tile
#define STAGES  2

// smem floats: xs[2 warps][2][STAGE] + w1s[800*4] + sw[240] = 8048 floats = 31.4KB
#define SMEM_FLOATS (2*STAGES*STAGE + KPAD*4 + 240)

__device__ __forceinline__ void cp_async16(unsigned dst, const float* src, int src_sz) {
    asm volatile("cp.async.cg.shared.global [%0], [%1], 16, %2;\n"
                 :: "r"(dst), "l"(src), "r"(src_sz));
}
__device__ __forceinline__ void cp_commit() {
    asm volatile("cp.async.commit_group;\n" ::: "memory");
}
template<int N>
__device__ __forceinline__ void cp_wait() {
    asm volatile("cp.async.wait_group %0;\n" :: "n"(N) : "memory");
}

__global__ void __launch_bounds__(BLOCKT) qhybrid_kernel(
    const float* __restrict__ x,
    const float* __restrict__ W1, const float* __restrict__ b1,
    const float* __restrict__ qw,
    const float* __restrict__ W2, const float* __restrict__ b2,
    const float* __restrict__ W3, const float* __restrict__ b3,
    float* __restrict__ out, int B)
{
    extern __shared__ float smem[];
    float* xs  = smem;                       // [2][2][32][36]
    float* w1s = smem + 2 * STAGES * STAGE;  // [800][4]
    float* sw  = w1s + KPAD * 4;             // small weights

    const int tid  = threadIdx.x;
    const int lane = tid & 31;
    const int wrp  = tid >> 5;               // 0..1
    const int rr   = lane >> 3;              // staging row group 0..3
    const int cc   = lane & 7;               // col chunk 0..7

    const long sbase = (long)blockIdx.x * BLOCKT + wrp * 32;  // warp's first sample
    const float* srow0 = x + (sbase + rr) * (long)KDIM;       // staging base row

    float* wbuf = xs + wrp * STAGES * STAGE;
    const unsigned wbuf_u = (unsigned)__cvta_generic_to_shared(wbuf);
    const unsigned dst0 = wbuf_u + (unsigned)((rr * XSTRIDE + cc * 4) * 4);

    // row validity for the 8 staging rows (rr + 4i)
    int rsz[8];
    #pragma unroll
    for (int i = 0; i < 8; i++)
        rsz[i] = (sbase + rr + 4 * i < (long)B) ? 16 : 0;

    // ---- prologue: tile 0 in flight (warp-private) ----
    {
        const int col = cc * 4;                   // kt=0
        #pragma unroll
        for (int i = 0; i < 8; i++)
            cp_async16(dst0 + (unsigned)(i * 4 * XSTRIDE * 4),
                       srow0 + (long)i * 4 * KDIM + col, rsz[i]);
        cp_commit();
    }

    // ---- preload W1 (zero-padded rows 784..799) + small weights ----
    for (int r = tid; r < KPAD; r += BLOCKT) {
        float4 v = make_float4(0.f, 0.f, 0.f, 0.f);
        if (r < KDIM) v = __ldg((const float4*)W1 + r);
        ((float4*)w1s)[r] = v;
    }
    // b1@0(4) qw@4(8) W2@12(128) b2@140(32) W3@172(64) b3@236(2)
    if (tid < 4)  sw[tid]      = b1[tid];
    if (tid < 8)  sw[4 + tid]  = qw[tid];
    for (int j = tid; j < 128; j += BLOCKT) sw[12 + j] = W2[j];
    if (tid < 32) sw[140 + tid] = b2[tid];
    for (int j = tid; j < 64; j += BLOCKT)  sw[172 + j] = W3[j];
    if (tid < 2)  sw[236 + tid] = b3[tid];
    __syncthreads();   // the ONLY block barrier: publish w1s/sw

    float acc[4] = {0.f, 0.f, 0.f, 0.f};

    // ---- GEMM mainloop: warp-autonomous double-buffered pipeline, no BAR ----
    #pragma unroll 1
    for (int kt = 0; kt < NT; kt++) {
        if (kt < NT - 1) {
            // prefetch tile kt+1 into buffer (kt+1)&1 (this warp's own reads
            // of that buffer finished in iter kt-1; warp is lockstep)
            const int col = (kt + 1) * TILE_K + cc * 4;
            const int csz = (col < KDIM) ? 16 : 0;   // zero-fill tail tile
            const unsigned d = dst0 + (unsigned)(((kt + 1) & 1) * STAGE * 4);
            #pragma unroll
            for (int i = 0; i < 8; i++)
                cp_async16(d + (unsigned)(i * 4 * XSTRIDE * 4),
                           srow0 + (long)i * 4 * KDIM + col, rsz[i] & csz);
            cp_commit();
            cp_wait<1>();     // tile kt complete (kt+1 still in flight)
        } else {
            cp_wait<0>();
        }
        __syncwarp();         // cross-lane visibility of tile kt (no BAR)

        // compute tile kt: this lane's sample = lane
        const float* xr = wbuf + (kt & 1) * STAGE + lane * XSTRIDE;
        const int colbase = kt * TILE_K;
        #pragma unroll
        for (int jj = 0; jj < 8; jj++) {
            float4 xv = *(const float4*)(xr + jj * 4);
            const float* wp = w1s + (colbase + jj * 4) * 4;
            float4 wa = *(const float4*)(wp);
            float4 wb = *(const float4*)(wp + 4);
            float4 wc = *(const float4*)(wp + 8);
            float4 wd = *(const float4*)(wp + 12);
            acc[0] = fmaf(xv.x, wa.x, acc[0]); acc[1] = fmaf(xv.x, wa.y, acc[1]);
            acc[2] = fmaf(xv.x, wa.z, acc[2]); acc[3] = fmaf(xv.x, wa.w, acc[3]);
            acc[0] = fmaf(xv.y, wb.x, acc[0]); acc[1] = fmaf(xv.y, wb.y, acc[1]);
            acc[2] = fmaf(xv.y, wb.z, acc[2]); acc[3] = fmaf(xv.y, wb.w, acc[3]);
            acc[0] = fmaf(xv.z, wc.x, acc[0]); acc[1] = fmaf(xv.z, wc.y, acc[1]);
            acc[2] = fmaf(xv.z, wc.z, acc[2]); acc[3] = fmaf(xv.z, wc.w, acc[3]);
            acc[0] = fmaf(xv.w, wd.x, acc[0]); acc[1] = fmaf(xv.w, wd.y, acc[1]);
            acc[2] = fmaf(xv.w, wd.z, acc[2]); acc[3] = fmaf(xv.w, wd.w, acc[3]);
        }
        __syncwarp();         // all lanes done reading buf kt&1 before refill
    }

    // ---- angles = relu(pre + b1) ----
    float cq[4], sq[4];
    #pragma unroll
    for (int q = 0; q < 4; q++) {
        float ang = fmaxf(acc[q] + sw[q], 0.f);
        __sincosf(0.5f * ang, &sq[q], &cq[q]);
    }

    // ---- 4-qubit statevector in registers ----
    float re[16], im[16];
    #pragma unroll
    for (int i = 0; i < 16; i++) {
        float m = 1.f;
        #pragma unroll
        for (int q = 0; q < 4; q++) m *= ((i >> (3 - q)) & 1) ? sq[q] : cq[q];
        int k = __popc(i) & 3;  // phase (-i)^k
        re[i] = (k == 0) ? m : ((k == 2) ? -m : 0.f);
        im[i] = (k == 1) ? -m : ((k == 3) ? m : 0.f);
    }

    // ---- BasicEntanglerLayers: RX(w[l,q]) then CNOT ring ----
    #pragma unroll
    for (int l = 0; l < 2; l++) {
        #pragma unroll
        for (int q = 0; q < 4; q++) {
            float cg, sg;
            __sincosf(0.5f * sw[4 + l * 4 + q], &sg, &cg);
            const int mask = 8 >> q;
            #pragma unroll
            for (int i = 0; i < 16; i++) {
                if (i & mask) continue;
                const int i1 = i | mask;
                float r0 = re[i], ii0 = im[i], r1 = re[i1], ii1 = im[i1];
                re[i]  = fmaf(cg, r0,  sg * ii1);
                im[i]  = fmaf(cg, ii0, -sg * r1);
                re[i1] = fmaf(cg, r1,  sg * ii0);
                im[i1] = fmaf(cg, ii1, -sg * r0);
            }
        }
        #pragma unroll
        for (int q = 0; q < 4; q++) {
            const int cmask = 8 >> q;
            const int tmask = 8 >> ((q + 1) & 3);
            #pragma unroll
            for (int i = 0; i < 16; i++) {
                if ((i & cmask) && !(i & tmask)) {
                    const int j = i | tmask;
                    float t = re[i]; re[i] = re[j]; re[j] = t;
                    t = im[i]; im[i] = im[j]; im[j] = t;
                }
            }
        }
    }

    // ---- <Z_q> expectation values ----
    float ez[4] = {0.f, 0.f, 0.f, 0.f};
    #pragma unroll
    for (int i = 0; i < 16; i++) {
        float p = re[i] * re[i] + im[i] * im[i];
        #pragma unroll
        for (int q = 0; q < 4; q++)
            ez[q] += ((i >> (3 - q)) & 1) ? -p : p;
    }
    #pragma unroll
    for (int q = 0; q < 4; q++)
        if (!(ez[q] == ez[q])) ez[q] = 0.f;  // NaN -> 0 (matches reference)

    // ---- post = relu(ez@W2 + b2); logits = post@W3 + b3; softmax ----
    float l0 = sw[236], l1 = sw[237];
    #pragma unroll
    for (int j = 0; j < 32; j++) {
        float pj = sw[140 + j];
        #pragma unroll
        for (int q = 0; q < 4; q++)
            pj = fmaf(ez[q], sw[12 + q * 32 + j], pj);
        pj = fmaxf(pj, 0.f);
        l0 = fmaf(pj, sw[172 + j * 2],     l0);
        l1 = fmaf(pj, sw[172 + j * 2 + 1], l1);
    }
    float mx = fmaxf(l0, l1);
    float e0 = __expf(l0 - mx);
    float e1 = __expf(l1 - mx);
    float inv = 1.f / (e0 + e1);

    long sg = sbase + lane;
    if (sg < (long)B) {
        float2 o = make_float2(e0 * inv, e1 * inv);
        *(float2*)(out + sg * 2) = o;
    }
}

extern "C" void kernel_launch(void* const* d_in, const int* in_sizes, int n_in,
                              void* d_out, int out_size) {
    const float* x  = (const float*)d_in[0];
    const float* W1 = (const float*)d_in[1];
    const float* b1 = (const float*)d_in[2];
    const float* qw = (const float*)d_in[3];
    const float* W2 = (const float*)d_in[4];
    const float* b2 = (const float*)d_in[5];
    const float* W3 = (const float*)d_in[6];
    const float* b3 = (const float*)d_in[7];
    float* out = (float*)d_out;

    int B = in_sizes[0] / KDIM;
    int grid = (B + BLOCKT - 1) / BLOCKT;       // 1024 blocks
    size_t smem_bytes = SMEM_FLOATS * sizeof(float);  // ~31.4 KB
    cudaFuncSetAttribute(qhybrid_kernel,
                         cudaFuncAttributeMaxDynamicSharedMemorySize,
                         (int)smem_bytes);
    qhybrid_kernel<<<grid, BLOCKT, smem_bytes>>>(x, W1, b1, qw, W2, b2, W3, b3, out, B);
}